// round 15
// baseline (speedup 1.0000x reference)
#include <cuda_runtime.h>
#include <cuda_fp16.h>
#include <cstdint>

#define BB   16
#define CC   256
#define CHALF 128
#define CQ   32
#define HW   9216
#define NPIXF 9216.0f

// ---- scratch (device globals; no runtime allocation allowed) ----
__device__ __align__(256) __half g_fhi[(size_t)BB*CC*HW];
__device__ __align__(256) __half g_flo[(size_t)BB*CC*HW];
__device__ __align__(256) __half g_qnhi[(size_t)BB*CQ*HW];
__device__ __align__(256) __half g_knhi[(size_t)BB*CQ*HW];
__device__ __align__(256) __half g_knlo[(size_t)BB*CQ*HW];
__device__ __align__(256) __half g_whiT[CC*CC];    // W^T hi  [k][m]
__device__ __align__(256) __half g_wloT[CC*CC];    // W^T lo  [k][m]
__device__ __align__(256) __half g_qkwhi[CC*64];   // [c][m] m<32:q, else k
__device__ __align__(256) __half g_qkwlo[CC*64];
__device__ __align__(256) __half g_mthi[BB*CC*CQ]; // matrix^T [b][c][m]
__device__ __align__(256) __half g_mtlo[BB*CC*CQ];
__device__ float g_G  [BB*CQ*CC];
__device__ float g_fsum[BB*CC];
__device__ float g_knsum[BB*CQ];
__device__ float g_vsum[BB*CC];
__device__ float g_bn_a[CC];
__device__ float g_bn_b[CC];

// =================== PTX helpers (sm_80-era, legal on sm_103 PTX) ===================
__device__ __forceinline__ uint32_t smem_u32(const void* p) {
    uint32_t a;
    asm("{ .reg .u64 t; cvta.to.shared.u64 t, %1; cvt.u32.u64 %0, t; }" : "=r"(a) : "l"(p));
    return a;
}
#define CP_ASYNC16(dst, src) \
    asm volatile("cp.async.cg.shared.global [%0], [%1], 16;" :: "r"(dst), "l"(src) : "memory")
#define CP_COMMIT() asm volatile("cp.async.commit_group;" ::: "memory")
#define CP_WAIT(n)  asm volatile("cp.async.wait_group %0;" :: "n"(n) : "memory")

#define LDSM_X4_T(r0, r1, r2, r3, addr) \
    asm volatile("ldmatrix.sync.aligned.m8n8.x4.trans.shared.b16 {%0,%1,%2,%3}, [%4];" \
                 : "=r"(r0), "=r"(r1), "=r"(r2), "=r"(r3) : "r"(addr))
#define LDSM_X4(r0, r1, r2, r3, addr) \
    asm volatile("ldmatrix.sync.aligned.m8n8.x4.shared.b16 {%0,%1,%2,%3}, [%4];" \
                 : "=r"(r0), "=r"(r1), "=r"(r2), "=r"(r3) : "r"(addr))

#define MMA16816(d, a, b) \
    asm volatile("mma.sync.aligned.m16n8k16.row.col.f32.f16.f16.f32 " \
                 "{%0,%1,%2,%3}, {%4,%5,%6,%7}, {%8,%9}, {%0,%1,%2,%3};" \
                 : "+f"((d)[0]), "+f"((d)[1]), "+f"((d)[2]), "+f"((d)[3]) \
                 : "r"((a)[0]), "r"((a)[1]), "r"((a)[2]), "r"((a)[3]), \
                   "r"((b)[0]), "r"((b)[1]))

// ---------------------------------------------------------------
// K0: zero accumulators, fold BN, build fp16 hi/lo weights
// ---------------------------------------------------------------
__global__ void k_setup(const float* __restrict__ bn_scale, const float* __restrict__ bn_bias,
                        const float* __restrict__ bn_mean,  const float* __restrict__ bn_var,
                        const float* __restrict__ conv_w,
                        const float* __restrict__ qw, const float* __restrict__ kw) {
    int t = blockIdx.x * blockDim.x + threadIdx.x;
    int stride = gridDim.x * blockDim.x;
    for (int i = t; i < BB*CQ*CC; i += stride) g_G[i] = 0.f;
    for (int i = t; i < BB*CC;    i += stride) g_fsum[i] = 0.f;
    for (int i = t; i < BB*CQ;    i += stride) g_knsum[i] = 0.f;
    for (int i = t; i < CC*CC;    i += stride) {
        int k = i >> 8, m = i & 255;
        float w = conv_w[m * CC + k];
        __half hi = __float2half(w);
        g_whiT[i] = hi;
        g_wloT[i] = __float2half(w - __half2float(hi));
    }
    for (int i = t; i < CC*64; i += stride) {
        int c = i >> 6, mm = i & 63;
        float w = (mm < 32) ? qw[mm * CC + c] : kw[(mm - 32) * CC + c];
        __half hi = __float2half(w);
        g_qkwhi[i] = hi;
        g_qkwlo[i] = __float2half(w - __half2float(hi));
    }
    if (t < CC) {
        float inv = rsqrtf(bn_var[t] + 1e-5f);
        float a = bn_scale[t] * inv;
        g_bn_a[t] = a;
        g_bn_b[t] = bn_bias[t] - bn_mean[t] * a;
    }
}

// ---------------------------------------------------------------
// K1: conv1x1 + BN + ReLU via mma.sync fp16, 2-term split on W
// ---------------------------------------------------------------
#define CONV_SMEM 81920
__global__ __launch_bounds__(512, 1) void k_conv_mma(const float* __restrict__ fsp,
                                                     const float* __restrict__ fcp) {
    extern __shared__ __align__(128) char smem[];
    const uint32_t smemb = smem_u32(smem);
    const int t    = threadIdx.x;
    const int lane = t & 31;
    const int wid  = t >> 5;
    const int n0   = blockIdx.x * 128;
    const int b    = blockIdx.y;
    const int wm   = (wid >> 2) * 64;
    const int wn   = (wid & 3) * 32;

    float acc[4][4][4];
    #pragma unroll
    for (int i = 0; i < 4; i++)
        #pragma unroll
        for (int j = 0; j < 4; j++)
            #pragma unroll
            for (int q = 0; q < 4; q++) acc[i][j][q] = 0.f;

    const int xr = t >> 4;
    const int xc = (t & 15) * 8;
    float4 X0, X1;
    {
        int cg = xr;
        const float* p = (cg < CHALF ? fsp + ((size_t)b * CHALF + cg) * HW
                                     : fcp + ((size_t)b * CHALF + cg - CHALF) * HW) + n0 + xc;
        X0 = *(const float4*)p; X1 = *(const float4*)(p + 4);
    }

    auto loadA = [&](int kc, int s) {
        #pragma unroll
        for (int p = 0; p < 4; p++) {
            int idx = t + p * 512;
            int h = idx >> 10, rem = idx & 1023;
            int r = rem >> 5, c = rem & 31;
            const __half* src = (h ? g_wloT : g_whiT) + (size_t)(kc * 32 + r) * CC + c * 8;
            uint32_t dst = smemb + s * 32768 + h * 16384 + r * 512 + ((c ^ (r & 7)) << 4);
            CP_ASYNC16(dst, src);
        }
        CP_COMMIT();
    };

    loadA(0, 0);

    for (int kc = 0; kc < 8; kc++) {
        const int s = kc & 1;
        {
            float xv[8] = {X0.x, X0.y, X0.z, X0.w, X1.x, X1.y, X1.z, X1.w};
            __align__(16) __half hv[8];
            #pragma unroll
            for (int q = 0; q < 8; q++) hv[q] = __float2half(xv[q]);
            int c = t & 15;
            uint32_t off = 65536 + s * 8192 + xr * 256 + ((c ^ (xr & 7)) << 4);
            *(uint4*)(smem + off) = *(uint4*)hv;
        }
        if (kc < 7) { loadA(kc + 1, s ^ 1); CP_WAIT(1); }
        else        { CP_WAIT(0); }
        __syncthreads();

        if (kc < 7) {
            int cg = (kc + 1) * 32 + xr;
            const float* p = (cg < CHALF ? fsp + ((size_t)b * CHALF + cg) * HW
                                         : fcp + ((size_t)b * CHALF + cg - CHALF) * HW) + n0 + xc;
            X0 = *(const float4*)p; X1 = *(const float4*)(p + 4);
        }

        const int l = lane & 7, g = lane >> 3;
        #pragma unroll
        for (int ks8 = 0; ks8 < 2; ks8++) {
            const int ks = ks8 * 16;
            uint32_t Bf[4][2];
            #pragma unroll
            for (int jp = 0; jp < 2; jp++) {
                int r = ks + ((g & 1) << 3) + l;
                int c = (wn >> 3) + jp * 2 + (g >> 1);
                uint32_t ad = smemb + 65536 + s * 8192 + r * 256 + ((c ^ (r & 7)) << 4);
                uint32_t q0, q1, q2, q3;
                LDSM_X4_T(q0, q1, q2, q3, ad);
                Bf[jp*2][0]=q0; Bf[jp*2][1]=q1; Bf[jp*2+1][0]=q2; Bf[jp*2+1][1]=q3;
            }
            #pragma unroll
            for (int i = 0; i < 4; i++) {
                uint32_t Ah[4], Al[4];
                {
                    int r = ks + ((g >> 1) << 3) + l;
                    int c = ((wm + i * 16) >> 3) + (g & 1);
                    uint32_t boff = r * 512 + ((c ^ (r & 7)) << 4);
                    LDSM_X4_T(Ah[0], Ah[1], Ah[2], Ah[3], smemb + s * 32768 + boff);
                    LDSM_X4_T(Al[0], Al[1], Al[2], Al[3], smemb + s * 32768 + 16384 + boff);
                }
                #pragma unroll
                for (int j = 0; j < 4; j++) {
                    MMA16816(acc[i][j], Ah, Bf[j]);
                    MMA16816(acc[i][j], Al, Bf[j]);
                }
            }
        }
        __syncthreads();
    }

    // ---- epilogue: BN + ReLU, store feat fp16 hi/lo, fsum ----
    #pragma unroll
    for (int i = 0; i < 4; i++) {
        int mlo = wm + i * 16 + (lane >> 2);
        int mhi = mlo + 8;
        float a0 = g_bn_a[mlo], c0 = g_bn_b[mlo];
        float a1 = g_bn_a[mhi], c1 = g_bn_b[mhi];
        float rs0 = 0.f, rs1 = 0.f;
        size_t rowlo = ((size_t)b * CC + mlo) * HW;
        size_t rowhi = ((size_t)b * CC + mhi) * HW;
        #pragma unroll
        for (int j = 0; j < 4; j++) {
            int n = n0 + wn + j * 8 + (lane & 3) * 2;
            float y00 = fmaxf(fmaf(acc[i][j][0], a0, c0), 0.f);
            float y01 = fmaxf(fmaf(acc[i][j][1], a0, c0), 0.f);
            float y10 = fmaxf(fmaf(acc[i][j][2], a1, c1), 0.f);
            float y11 = fmaxf(fmaf(acc[i][j][3], a1, c1), 0.f);
            __half2 h0, h1, l0v, l1v;
            h0.x = __float2half(y00); h0.y = __float2half(y01);
            h1.x = __float2half(y10); h1.y = __float2half(y11);
            l0v.x = __float2half(y00 - __half2float(h0.x));
            l0v.y = __float2half(y01 - __half2float(h0.y));
            l1v.x = __float2half(y10 - __half2float(h1.x));
            l1v.y = __float2half(y11 - __half2float(h1.y));
            *(__half2*)&g_fhi[rowlo + n] = h0;
            *(__half2*)&g_fhi[rowhi + n] = h1;
            *(__half2*)&g_flo[rowlo + n] = l0v;
            *(__half2*)&g_flo[rowhi + n] = l1v;
            rs0 += y00 + y01; rs1 += y10 + y11;
        }
        rs0 += __shfl_xor_sync(0xFFFFFFFF, rs0, 1);
        rs0 += __shfl_xor_sync(0xFFFFFFFF, rs0, 2);
        rs1 += __shfl_xor_sync(0xFFFFFFFF, rs1, 1);
        rs1 += __shfl_xor_sync(0xFFFFFFFF, rs1, 2);
        if ((lane & 3) == 0) {
            atomicAdd(&g_fsum[b * CC + mlo], rs0);
            atomicAdd(&g_fsum[b * CC + mhi], rs1);
        }
    }
}

// ---------------------------------------------------------------
// K2: QK = Wqk @ feat via HMMA; 2-term split on Wqk, feat hi only.
// ---------------------------------------------------------------
#define QK_SMEM 66816
__global__ __launch_bounds__(256, 1) void k_qk_mma(const float* __restrict__ qb,
                                                   const float* __restrict__ kb) {
    extern __shared__ __align__(128) char smem[];
    const uint32_t smemb = smem_u32(smem);
    const int t    = threadIdx.x;
    const int lane = t & 31;
    const int wid  = t >> 5;
    const int n0   = blockIdx.x * 128;
    const int b    = blockIdx.y;
    const int wm   = (wid >> 2) * 32;
    const int wn   = (wid & 3) * 32;

    float acc[2][4][4];
    #pragma unroll
    for (int i = 0; i < 2; i++)
        #pragma unroll
        for (int j = 0; j < 4; j++)
            #pragma unroll
            for (int q = 0; q < 4; q++) acc[i][j][q] = 0.f;

    auto loadAB = [&](int kc, int s) {
        #pragma unroll
        for (int p = 0; p < 2; p++) {
            int idx = t + p * 256;
            int h = idx >> 8, rem = idx & 255;
            int r = rem >> 3, c = rem & 7;
            const __half* src = (h ? g_qkwlo : g_qkwhi) + (kc * 32 + r) * 64 + c * 8;
            CP_ASYNC16(smemb + s * 8192 + h * 4096 + r * 128 + ((c ^ (r & 7)) << 4), src);
        }
        #pragma unroll
        for (int p = 0; p < 2; p++) {
            int idx = t + p * 256;
            int r = idx >> 4, c = idx & 15;
            const __half* src = g_fhi + ((size_t)b * CC + kc * 32 + r) * HW + n0 + c * 8;
            CP_ASYNC16(smemb + 16384 + s * 8192 + r * 256 + ((c ^ (r & 7)) << 4), src);
        }
        CP_COMMIT();
    };

    loadAB(0, 0);

    for (int kc = 0; kc < 8; kc++) {
        const int s = kc & 1;
        if (kc < 7) { loadAB(kc + 1, s ^ 1); CP_WAIT(1); }
        else        { CP_WAIT(0); }
        __syncthreads();

        const int l = lane & 7, g = lane >> 3;
        #pragma unroll
        for (int ks8 = 0; ks8 < 2; ks8++) {
            const int ks = ks8 * 16;
            uint32_t Bf[4][2];
            #pragma unroll
            for (int jp = 0; jp < 2; jp++) {
                int r = ks + ((g & 1) << 3) + l;
                int c = (wn >> 3) + jp * 2 + (g >> 1);
                uint32_t ad = smemb + 16384 + s * 8192 + r * 256 + ((c ^ (r & 7)) << 4);
                uint32_t q0, q1, q2, q3;
                LDSM_X4_T(q0, q1, q2, q3, ad);
                Bf[jp*2][0]=q0; Bf[jp*2][1]=q1; Bf[jp*2+1][0]=q2; Bf[jp*2+1][1]=q3;
            }
            #pragma unroll
            for (int i = 0; i < 2; i++) {
                uint32_t Ah[4], Al[4];
                {
                    int r = ks + ((g >> 1) << 3) + l;
                    int c = ((wm + i * 16) >> 3) + (g & 1);
                    uint32_t boff = r * 128 + ((c ^ (r & 7)) << 4);
                    LDSM_X4_T(Ah[0], Ah[1], Ah[2], Ah[3], smemb + s * 8192 + boff);
                    LDSM_X4_T(Al[0], Al[1], Al[2], Al[3], smemb + s * 8192 + 4096 + boff);
                }
                #pragma unroll
                for (int j = 0; j < 4; j++) {
                    MMA16816(acc[i][j], Ah, Bf[j]);
                    MMA16816(acc[i][j], Al, Bf[j]);
                }
            }
        }
        __syncthreads();
    }

    float* qk = (float*)(smem + 32768);   // [64][129]
    #pragma unroll
    for (int i = 0; i < 2; i++) {
        int mlo = wm + i * 16 + (lane >> 2);
        int mhi = mlo + 8;
        float blo = (mlo < 32) ? qb[mlo] : kb[mlo - 32];
        float bhi = (mhi < 32) ? qb[mhi] : kb[mhi - 32];
        #pragma unroll
        for (int j = 0; j < 4; j++) {
            int col = wn + j * 8 + (lane & 3) * 2;
            qk[mlo * 129 + col]     = acc[i][j][0] + blo;
            qk[mlo * 129 + col + 1] = acc[i][j][1] + blo;
            qk[mhi * 129 + col]     = acc[i][j][2] + bhi;
            qk[mhi * 129 + col + 1] = acc[i][j][3] + bhi;
        }
    }
    __syncthreads();

    {
        int n = t & 127, h = t >> 7;
        float ss = 0.f;
        #pragma unroll
        for (int m = 0; m < 32; m++) { float v = qk[(h * 32 + m) * 129 + n]; ss = fmaf(v, v, ss); }
        float inv = rsqrtf(ss);
        size_t base = (size_t)b * CQ * HW + n0 + n;
        if (h == 0) {
            #pragma unroll
            for (int m = 0; m < 32; m++) {
                float v = qk[m * 129 + n] * inv;
                g_qnhi[base + (size_t)m * HW] = __float2half(v);
            }
        } else {
            #pragma unroll
            for (int m = 0; m < 32; m++) {
                float v = qk[(32 + m) * 129 + n] * inv;
                qk[(32 + m) * 129 + n] = v;
                __half vh = __float2half(v);
                g_knhi[base + (size_t)m * HW] = vh;
                g_knlo[base + (size_t)m * HW] = __float2half(v - __half2float(vh));
            }
        }
    }
    __syncthreads();
    float* part = (float*)(smem + 65792);  // [32][8]
    {
        int m = t >> 3, seg = t & 7;
        float s = 0.f;
        #pragma unroll
        for (int j = 0; j < 16; j++) s += qk[(32 + m) * 129 + seg * 16 + j];
        part[m * 8 + seg] = s;
    }
    __syncthreads();
    if (t < 32) {
        float s = 0.f;
        #pragma unroll
        for (int j = 0; j < 8; j++) s += part[t * 8 + j];
        atomicAdd(&g_knsum[b * CQ + t], s);
    }
}

// ---------------------------------------------------------------
// K3: G^T[c][m] = sum_n feat[c][n]*Kn[m][n]; 2-term split on Kn, feat hi.
// ---------------------------------------------------------------
#define G_SMEM 81920
__global__ __launch_bounds__(256, 1) void k_G_mma() {
    extern __shared__ __align__(128) char smem[];
    const uint32_t smemb = smem_u32(smem);
    const int t    = threadIdx.x;
    const int lane = t & 31;
    const int wid  = t >> 5;
    const int b    = blockIdx.y;
    const int n0   = blockIdx.x * 512;
    const int wc   = wid * 32;

    float acc[2][4][4];
    #pragma unroll
    for (int i = 0; i < 2; i++)
        #pragma unroll
        for (int j = 0; j < 4; j++)
            #pragma unroll
            for (int q = 0; q < 4; q++) acc[i][j][q] = 0.f;

    auto loadAB = [&](int kc, int s) {
        int nb = n0 + kc * 64;
        #pragma unroll
        for (int p = 0; p < 8; p++) {
            int idx = t + p * 256;
            int r = idx >> 3, c = idx & 7;
            const __half* src = g_fhi + ((size_t)b * CC + r) * HW + nb + c * 8;
            CP_ASYNC16(smemb + s * 32768 + r * 128 + ((c ^ (r & 7)) << 4), src);
        }
        #pragma unroll
        for (int p = 0; p < 2; p++) {
            int idx = t + p * 256;
            int h = idx >> 8, rem = idx & 255;
            int r = rem >> 3, c = rem & 7;
            const __half* src = (h ? g_knlo : g_knhi)
                + ((size_t)b * CQ + r) * HW + nb + c * 8;
            CP_ASYNC16(smemb + 65536 + s * 8192 + h * 4096 + r * 128 + ((c ^ (r & 7)) << 4), src);
        }
        CP_COMMIT();
    };

    loadAB(0, 0);

    for (int kc = 0; kc < 8; kc++) {
        const int s = kc & 1;
        if (kc < 7) { loadAB(kc + 1, s ^ 1); CP_WAIT(1); }
        else        { CP_WAIT(0); }
        __syncthreads();

        #pragma unroll
        for (int ks8 = 0; ks8 < 4; ks8++) {
            const int kcol0 = ks8 * 2;
            uint32_t Bh[4][2], Bl[4][2];
            #pragma unroll
            for (int h = 0; h < 2; h++)
                #pragma unroll
                for (int jp = 0; jp < 2; jp++) {
                    int r = jp * 16 + ((lane & 16) >> 1) + (lane & 7);
                    int c = kcol0 + ((lane & 8) >> 3);
                    uint32_t ad = smemb + 65536 + s * 8192 + h * 4096
                                + r * 128 + ((c ^ (r & 7)) << 4);
                    uint32_t q0, q1, q2, q3;
                    LDSM_X4(q0, q1, q2, q3, ad);
                    if (h == 0) { Bh[jp*2][0]=q0; Bh[jp*2][1]=q1; Bh[jp*2+1][0]=q2; Bh[jp*2+1][1]=q3; }
                    else        { Bl[jp*2][0]=q0; Bl[jp*2][1]=q1; Bl[jp*2+1][0]=q2; Bl[jp*2+1][1]=q3; }
                }
            #pragma unroll
            for (int i = 0; i < 2; i++) {
                uint32_t Ah[4];
                {
                    int r = wc + i * 16 + (lane & 15);
                    int c = kcol0 + ((lane & 16) >> 4);
                    uint32_t boff = r * 128 + ((c ^ (r & 7)) << 4);
                    LDSM_X4(Ah[0], Ah[1], Ah[2], Ah[3], smemb + s * 32768 + boff);
                }
                #pragma unroll
                for (int j = 0; j < 4; j++) {
                    MMA16816(acc[i][j], Ah, Bh[j]);
                    MMA16816(acc[i][j], Ah, Bl[j]);
                }
            }
        }
        __syncthreads();
    }

    #pragma unroll
    for (int i = 0; i < 2; i++) {
        int clo = wc + i * 16 + (lane >> 2);
        int chi = clo + 8;
        #pragma unroll
        for (int j = 0; j < 4; j++) {
            int m = j * 8 + (lane & 3) * 2;
            atomicAdd(&g_G[((size_t)b * CQ + m)     * CC + clo], acc[i][j][0]);
            atomicAdd(&g_G[((size_t)b * CQ + m + 1) * CC + clo], acc[i][j][1]);
            atomicAdd(&g_G[((size_t)b * CQ + m)     * CC + chi], acc[i][j][2]);
            atomicAdd(&g_G[((size_t)b * CQ + m + 1) * CC + chi], acc[i][j][3]);
        }
    }
}

// ---------------------------------------------------------------
// K4: matrix = G @ v_w^T + v_b x knsum -> fp16 hi/lo [c][m];
//     vsum = v_w @ fsum + N*v_b.  grid (8 c-tiles, 16 b).
// ---------------------------------------------------------------
#define MAT_SMEM 68096
__global__ __launch_bounds__(256, 1) void k_matrix(const float* __restrict__ vw,
                                                   const float* __restrict__ vb) {
    extern __shared__ __align__(16) float sm[];
    float* GsT   = sm;                        // [256][33]
    float* vws   = sm + 256 * 33;             // [32][260]
    float* fsums = sm + 256 * 33 + 32 * 260;  // [256]
    const int t  = threadIdx.x;
    const int b  = blockIdx.y;
    const int c0 = blockIdx.x * 32;

    {
        int rr = t >> 3, kseg = (t & 7) * 32;
        const float* gp = g_G + ((size_t)b * CQ + rr) * CC + kseg;
        #pragma unroll
        for (int j = 0; j < 8; j++) {
            float4 v = *(const float4*)&gp[j * 4];
            GsT[(kseg + j*4 + 0) * 33 + rr] = v.x;
            GsT[(kseg + j*4 + 1) * 33 + rr] = v.y;
            GsT[(kseg + j*4 + 2) * 33 + rr] = v.z;
            GsT[(kseg + j*4 + 3) * 33 + rr] = v.w;
        }
        const float* vp = vw + (size_t)(c0 + rr) * CC + kseg;
        #pragma unroll
        for (int j = 0; j < 8; j++)
            *(float4*)&vws[rr * 260 + kseg + j * 4] = *(const float4*)&vp[j * 4];
    }
    fsums[t] = g_fsum[b * CC + t];
    __syncthreads();

    const int m = t & 31;
    const int w = t >> 5;
    float acc[4] = {0.f, 0.f, 0.f, 0.f};
    #pragma unroll 4
    for (int k = 0; k < CC; k++) {
        float gv = GsT[k * 33 + m];
        #pragma unroll
        for (int j = 0; j < 4; j++)
            acc[j] = fmaf(gv, vws[(w * 4 + j) * 260 + k], acc[j]);
    }
    float vs[4] = {0.f, 0.f, 0.f, 0.f};
    for (int k = m; k < CC; k += 32) {
        float fv = fsums[k];
        #pragma unroll
        for (int j = 0; j < 4; j++)
            vs[j] = fmaf(vws[(w * 4 + j) * 260 + k], fv, vs[j]);
    }
    #pragma unroll
    for (int j = 0; j < 4; j++)
        #pragma unroll
        for (int o = 16; o; o >>= 1)
            vs[j] += __shfl_xor_sync(0xFFFFFFFF, vs[j], o);

    float kn = g_knsum[b * CQ + m];
    #pragma unroll
    for (int j = 0; j < 4; j++) {
        int c = c0 + w * 4 + j;
        float val = acc[j] + vb[c] * kn;
        __half hi = __float2half(val);
        size_t idx = ((size_t)b * CC + c) * CQ + m;
        g_mthi[idx] = hi;
        g_mtlo[idx] = __float2half(val - __half2float(hi));
        if (m == 0) g_vsum[b * CC + c] = vs[j] + NPIXF * vb[c];
    }
}

// ---------------------------------------------------------------
// K5: ms = matrix^T @ Qn + vsum; 2-term split on mt, Qn hi only.
//     wv staged to smem; fully-coalesced streaming epilogue.
// SMEM: A [2h][256][128B]=64K @0 ; B @65536 [32][256B]=8K ;
//       wvs (reuses 0..67584 after MMA) [128][132] f32 ;
//       tails @73728 f[128]; vsums @74240 f[256]; total 75264
// ---------------------------------------------------------------
#define FIN_SMEM 75264
__global__ __launch_bounds__(512, 1) void k_final_mma(const float* __restrict__ gamma,
                                                      float* __restrict__ out) {
    extern __shared__ __align__(128) char smem[];
    const uint32_t smemb = smem_u32(smem);
    const int t    = threadIdx.x;
    const int lane = t & 31;
    const int wid  = t >> 5;
    const int n0   = blockIdx.x * 128;
    const int b    = blockIdx.y;
    const int wm   = (wid >> 2) * 64;
    const int wn   = (wid & 3) * 32;

    float* tails = (float*)(smem + 73728);
    float* vsums = (float*)(smem + 74240);
    const float gw = gamma[0];

    #pragma unroll
    for (int p = 0; p < 4; p++) {        // A: mt 2048 ops
        int idx = t + p * 512;
        int h = idx >> 10, rem = idx & 1023;
        int r = rem >> 2, c = rem & 3;
        const __half* src = (h ? g_mtlo : g_mthi) + ((size_t)b * CC + r) * CQ + c * 8;
        CP_ASYNC16(smemb + h * 32768 + r * 128 + ((c ^ (r & 7)) << 4), src);
    }
    {                                    // B: qnhi 512 ops
        int r = t >> 4, c = t & 15;
        const __half* src = g_qnhi + ((size_t)b * CQ + r) * HW + n0 + c * 8;
        CP_ASYNC16(smemb + 65536 + r * 256 + ((c ^ (r & 7)) << 4), src);
    }
    CP_COMMIT();
    if (t < 256) vsums[t] = g_vsum[b * CC + t];
    CP_WAIT(0);
    __syncthreads();

    if (t < 128) {
        int n = t;
        int cseg = n >> 3, off = (n & 7) * 2;
        float s = 0.f;
        #pragma unroll
        for (int m = 0; m < 32; m++) {
            uint32_t ad = 65536 + m * 256 + ((cseg ^ (m & 7)) << 4) + off;
            float qh = __half2float(*(__half*)(smem + ad));
            s = fmaf(qh, g_knsum[b * CQ + m] + 1e-6f, s);
        }
        tails[n] = gw / (NPIXF + s);     // gamma folded into tailor
    }
    __syncthreads();

    float acc[4][4][4];
    #pragma unroll
    for (int i = 0; i < 4; i++)
        #pragma unroll
        for (int j = 0; j < 4; j++)
            #pragma unroll
            for (int q = 0; q < 4; q++) acc[i][j][q] = 0.f;

    const int l = lane & 7, g = lane >> 3;
    #pragma unroll
    for (int ks8 = 0; ks8 < 2; ks8++) {
        const int ks = ks8 * 16;
        uint32_t Bf[4][2];
        #pragma unroll
        for (int jp = 0; jp < 2; jp++) {
            int r = ks + ((g & 1) << 3) + l;
            int c = (wn >> 3) + jp * 2 + (g >> 1);
            uint32_t ad = smemb + 65536 + r * 256 + ((c ^ (r & 7)) << 4);
            uint32_t q0, q1, q2, q3;
            LDSM_X4_T(q0, q1, q2, q3, ad);
            Bf[jp*2][0]=q0; Bf[jp*2][1]=q1; Bf[jp*2+1][0]=q2; Bf[jp*2+1][1]=q3;
        }
        #pragma unroll
        for (int i = 0; i < 4; i++) {
            uint32_t Ah[4], Al[4];
            {
                int r = wm + i * 16 + (lane & 15);
                int c = ks8 * 2 + ((lane & 16) >> 4);
                uint32_t boff = r * 128 + ((c ^ (r & 7)) << 4);
                LDSM_X4(Ah[0], Ah[1], Ah[2], Ah[3], smemb + boff);
                LDSM_X4(Al[0], Al[1], Al[2], Al[3], smemb + 32768 + boff);
            }
            #pragma unroll
            for (int j = 0; j < 4; j++) {
                MMA16816(acc[i][j], Ah, Bf[j]);
                MMA16816(acc[i][j], Al, Bf[j]);
            }
        }
    }

    // ---- staged epilogue: wv -> smem per 128-channel half; coalesced stream ----
    float* wvs = (float*)smem;    // [128][132] fp32 (reuses dead A/B region)
    #pragma unroll
    for (int h = 0; h < 2; h++) {
        __syncthreads();          // A/B smem reads (and prev stream) complete
        if ((wm >> 7) == h) {
            const int relb = wm & 64;
            #pragma unroll
            for (int i = 0; i < 4; i++) {
                int rlo = relb + i * 16 + (lane >> 2);
                int cg  = wm + i * 16 + (lane >> 2);
                float vs0 = vsums[cg], vs1 = vsums[cg + 8];
                #pragma unroll
                for (int j = 0; j < 4; j++) {
                    int nl = wn + j * 8 + (lane & 3) * 2;
                    float t0 = tails[nl], t1 = tails[nl + 1];
                    float2 w0 = { (acc[i][j][0] + vs0) * t0, (acc[i][j][1] + vs0) * t1 };
                    float2 w1 = { (acc[i][j][2] + vs1) * t0, (acc[i][j][3] + vs1) * t1 };
                    *(float2*)&wvs[rlo * 132 + nl]       = w0;
                    *(float2*)&wvs[(rlo + 8) * 132 + nl] = w1;
                }
            }
        }
        __syncthreads();
        const size_t basec = ((size_t)b * CC + h * 128) * HW + n0;
        #pragma unroll
        for (int it = 0; it < 8; it++) {
            int idx = t + it * 512;
            int row = idx >> 5;
            int nq  = (idx & 31) * 4;
            size_t ga = basec + (size_t)row * HW + nq;
            __half2 fh[2], fl[2];
            *(uint2*)fh = *(const uint2*)&g_fhi[ga];
            *(uint2*)fl = *(const uint2*)&g_flo[ga];
            float4 wv = *(float4*)&wvs[row * 132 + nq];
            float f0 = __half2float(fh[0].x) + __half2float(fl[0].x);
            float f1 = __half2float(fh[0].y) + __half2float(fl[0].y);
            float f2 = __half2float(fh[1].x) + __half2float(fl[1].x);
            float f3 = __half2float(fh[1].y) + __half2float(fl[1].y);
            float4 o;
            o.x = fmaf(f0, f0 + wv.x, f0);
            o.y = fmaf(f1, f1 + wv.y, f1);
            o.z = fmaf(f2, f2 + wv.z, f2);
            o.w = fmaf(f3, f3 + wv.w, f3);
            *(float4*)&out[ga] = o;
        }
    }
}

// ---------------------------------------------------------------
extern "C" void kernel_launch(void* const* d_in, const int* in_sizes, int n_in,
                              void* d_out, int out_size) {
    const float* fsp      = (const float*)d_in[0];
    const float* fcp      = (const float*)d_in[1];
    const float* conv_w   = (const float*)d_in[2];
    const float* bn_scale = (const float*)d_in[3];
    const float* bn_bias  = (const float*)d_in[4];
    const float* bn_mean  = (const float*)d_in[5];
    const float* bn_var   = (const float*)d_in[6];
    const float* gamma    = (const float*)d_in[7];
    const float* q_w      = (const float*)d_in[8];
    const float* q_b      = (const float*)d_in[9];
    const float* k_w      = (const float*)d_in[10];
    const float* k_b      = (const float*)d_in[11];
    const float* v_w      = (const float*)d_in[12];
    const float* v_b      = (const float*)d_in[13];
    float* out = (float*)d_out;

    cudaFuncSetAttribute(k_conv_mma,  cudaFuncAttributeMaxDynamicSharedMemorySize, CONV_SMEM);
    cudaFuncSetAttribute(k_qk_mma,    cudaFuncAttributeMaxDynamicSharedMemorySize, QK_SMEM);
    cudaFuncSetAttribute(k_G_mma,     cudaFuncAttributeMaxDynamicSharedMemorySize, G_SMEM);
    cudaFuncSetAttribute(k_matrix,    cudaFuncAttributeMaxDynamicSharedMemorySize, MAT_SMEM);
    cudaFuncSetAttribute(k_final_mma, cudaFuncAttributeMaxDynamicSharedMemorySize, FIN_SMEM);

    k_setup<<<128, 256>>>(bn_scale, bn_bias, bn_mean, bn_var, conv_w, q_w, k_w);
    k_conv_mma <<<dim3(72, 16), 512, CONV_SMEM>>>(fsp, fcp);
    k_qk_mma   <<<dim3(72, 16), 256, QK_SMEM>>>(q_b, k_b);
    k_G_mma    <<<dim3(18, 16), 256, G_SMEM>>>();
    k_matrix   <<<dim3(8, 16),  256, MAT_SMEM>>>(v_w, v_b);
    k_final_mma<<<dim3(72, 16), 512, FIN_SMEM>>>(gamma, out);
}

// round 17
// speedup vs baseline: 1.1849x; 1.1849x over previous
#include <cuda_runtime.h>
#include <cuda_fp16.h>
#include <cstdint>

#define BB   16
#define CC   256
#define CHALF 128
#define CQ   32
#define HW   9216
#define NPIXF 9216.0f

// ---- scratch (device globals; no runtime allocation allowed) ----
__device__ __align__(256) __half g_fhi[(size_t)BB*CC*HW];
__device__ __align__(256) __half g_flo[(size_t)BB*CC*HW];
__device__ __align__(256) __half g_qnhi[(size_t)BB*CQ*HW];
__device__ __align__(256) __half g_knhi[(size_t)BB*CQ*HW];
__device__ __align__(256) __half g_knlo[(size_t)BB*CQ*HW];
__device__ __align__(256) __half g_whiT[CC*CC];    // W^T fp16 [k][m]
__device__ __align__(256) __half g_qkwhi[CC*64];   // [c][m] m<32:q, else k
__device__ __align__(256) __half g_qkwlo[CC*64];
__device__ __align__(256) __half g_mthi[BB*CC*CQ]; // matrix^T [b][c][m]
__device__ __align__(256) __half g_mtlo[BB*CC*CQ];
__device__ float g_G  [BB*CQ*CC];
__device__ float g_fsum[BB*CC];
__device__ float g_knsum[BB*CQ];
__device__ float g_vsum[BB*CC];
__device__ float g_bn_a[CC];
__device__ float g_bn_b[CC];

// =================== PTX helpers (sm_80-era, legal on sm_103 PTX) ===================
__device__ __forceinline__ uint32_t smem_u32(const void* p) {
    uint32_t a;
    asm("{ .reg .u64 t; cvta.to.shared.u64 t, %1; cvt.u32.u64 %0, t; }" : "=r"(a) : "l"(p));
    return a;
}
#define CP_ASYNC16(dst, src) \
    asm volatile("cp.async.cg.shared.global [%0], [%1], 16;" :: "r"(dst), "l"(src) : "memory")
#define CP_COMMIT() asm volatile("cp.async.commit_group;" ::: "memory")
#define CP_WAIT(n)  asm volatile("cp.async.wait_group %0;" :: "n"(n) : "memory")

#define LDSM_X4_T(r0, r1, r2, r3, addr) \
    asm volatile("ldmatrix.sync.aligned.m8n8.x4.trans.shared.b16 {%0,%1,%2,%3}, [%4];" \
                 : "=r"(r0), "=r"(r1), "=r"(r2), "=r"(r3) : "r"(addr))
#define LDSM_X4(r0, r1, r2, r3, addr) \
    asm volatile("ldmatrix.sync.aligned.m8n8.x4.shared.b16 {%0,%1,%2,%3}, [%4];" \
                 : "=r"(r0), "=r"(r1), "=r"(r2), "=r"(r3) : "r"(addr))

#define MMA16816(d, a, b) \
    asm volatile("mma.sync.aligned.m16n8k16.row.col.f32.f16.f16.f32 " \
                 "{%0,%1,%2,%3}, {%4,%5,%6,%7}, {%8,%9}, {%0,%1,%2,%3};" \
                 : "+f"((d)[0]), "+f"((d)[1]), "+f"((d)[2]), "+f"((d)[3]) \
                 : "r"((a)[0]), "r"((a)[1]), "r"((a)[2]), "r"((a)[3]), \
                   "r"((b)[0]), "r"((b)[1]))

// ---------------------------------------------------------------
// K0: zero accumulators, fold BN, build fp16 weights
// ---------------------------------------------------------------
__global__ void k_setup(const float* __restrict__ bn_scale, const float* __restrict__ bn_bias,
                        const float* __restrict__ bn_mean,  const float* __restrict__ bn_var,
                        const float* __restrict__ conv_w,
                        const float* __restrict__ qw, const float* __restrict__ kw) {
    int t = blockIdx.x * blockDim.x + threadIdx.x;
    int stride = gridDim.x * blockDim.x;
    for (int i = t; i < BB*CQ*CC; i += stride) g_G[i] = 0.f;
    for (int i = t; i < BB*CC;    i += stride) g_fsum[i] = 0.f;
    for (int i = t; i < BB*CQ;    i += stride) g_knsum[i] = 0.f;
    for (int i = t; i < CC*CC;    i += stride) {
        int k = i >> 8, m = i & 255;
        g_whiT[i] = __float2half(conv_w[m * CC + k]);
    }
    for (int i = t; i < CC*64; i += stride) {
        int c = i >> 6, mm = i & 63;
        float w = (mm < 32) ? qw[mm * CC + c] : kw[(mm - 32) * CC + c];
        __half hi = __float2half(w);
        g_qkwhi[i] = hi;
        g_qkwlo[i] = __float2half(w - __half2float(hi));
    }
    if (t < CC) {
        float inv = rsqrtf(bn_var[t] + 1e-5f);
        float a = bn_scale[t] * inv;
        g_bn_a[t] = a;
        g_bn_b[t] = bn_bias[t] - bn_mean[t] * a;
    }
}

// ---------------------------------------------------------------
// K1: conv1x1 + BN + ReLU via mma.sync fp16, SINGLE-term W
//     A = W^T fp16 (cp.async); B = X fp16 (reg convert + STS)
// SMEM: A [2s][32k][512B]=32K ; B @32768 [2s][32k][256B]=16K = 49152
// ---------------------------------------------------------------
#define CONV_SMEM 49152
__global__ __launch_bounds__(512, 1) void k_conv_mma(const float* __restrict__ fsp,
                                                     const float* __restrict__ fcp) {
    extern __shared__ __align__(128) char smem[];
    const uint32_t smemb = smem_u32(smem);
    const int t    = threadIdx.x;
    const int lane = t & 31;
    const int wid  = t >> 5;
    const int n0   = blockIdx.x * 128;
    const int b    = blockIdx.y;
    const int wm   = (wid >> 2) * 64;
    const int wn   = (wid & 3) * 32;

    float acc[4][4][4];
    #pragma unroll
    for (int i = 0; i < 4; i++)
        #pragma unroll
        for (int j = 0; j < 4; j++)
            #pragma unroll
            for (int q = 0; q < 4; q++) acc[i][j][q] = 0.f;

    const int xr = t >> 4;
    const int xc = (t & 15) * 8;
    float4 X0, X1;
    {
        int cg = xr;
        const float* p = (cg < CHALF ? fsp + ((size_t)b * CHALF + cg) * HW
                                     : fcp + ((size_t)b * CHALF + cg - CHALF) * HW) + n0 + xc;
        X0 = *(const float4*)p; X1 = *(const float4*)(p + 4);
    }

    auto loadA = [&](int kc, int s) {
        #pragma unroll
        for (int p = 0; p < 2; p++) {
            int idx = t + p * 512;
            int r = idx >> 5, c = idx & 31;
            const __half* src = g_whiT + (size_t)(kc * 32 + r) * CC + c * 8;
            uint32_t dst = smemb + s * 16384 + r * 512 + ((c ^ (r & 7)) << 4);
            CP_ASYNC16(dst, src);
        }
        CP_COMMIT();
    };

    loadA(0, 0);

    for (int kc = 0; kc < 8; kc++) {
        const int s = kc & 1;
        {
            float xv[8] = {X0.x, X0.y, X0.z, X0.w, X1.x, X1.y, X1.z, X1.w};
            __align__(16) __half hv[8];
            #pragma unroll
            for (int q = 0; q < 8; q++) hv[q] = __float2half(xv[q]);
            int c = t & 15;
            uint32_t off = 32768 + s * 8192 + xr * 256 + ((c ^ (xr & 7)) << 4);
            *(uint4*)(smem + off) = *(uint4*)hv;
        }
        if (kc < 7) { loadA(kc + 1, s ^ 1); CP_WAIT(1); }
        else        { CP_WAIT(0); }
        __syncthreads();

        if (kc < 7) {
            int cg = (kc + 1) * 32 + xr;
            const float* p = (cg < CHALF ? fsp + ((size_t)b * CHALF + cg) * HW
                                         : fcp + ((size_t)b * CHALF + cg - CHALF) * HW) + n0 + xc;
            X0 = *(const float4*)p; X1 = *(const float4*)(p + 4);
        }

        const int l = lane & 7, g = lane >> 3;
        #pragma unroll
        for (int ks8 = 0; ks8 < 2; ks8++) {
            const int ks = ks8 * 16;
            uint32_t Bf[4][2];
            #pragma unroll
            for (int jp = 0; jp < 2; jp++) {
                int r = ks + ((g & 1) << 3) + l;
                int c = (wn >> 3) + jp * 2 + (g >> 1);
                uint32_t ad = smemb + 32768 + s * 8192 + r * 256 + ((c ^ (r & 7)) << 4);
                uint32_t q0, q1, q2, q3;
                LDSM_X4_T(q0, q1, q2, q3, ad);
                Bf[jp*2][0]=q0; Bf[jp*2][1]=q1; Bf[jp*2+1][0]=q2; Bf[jp*2+1][1]=q3;
            }
            #pragma unroll
            for (int i = 0; i < 4; i++) {
                uint32_t Ah[4];
                {
                    int r = ks + ((g >> 1) << 3) + l;
                    int c = ((wm + i * 16) >> 3) + (g & 1);
                    uint32_t boff = r * 512 + ((c ^ (r & 7)) << 4);
                    LDSM_X4_T(Ah[0], Ah[1], Ah[2], Ah[3], smemb + s * 16384 + boff);
                }
                #pragma unroll
                for (int j = 0; j < 4; j++)
                    MMA16816(acc[i][j], Ah, Bf[j]);
            }
        }
        __syncthreads();
    }

    // ---- epilogue: BN + ReLU, store feat fp16 hi/lo, fsum ----
    #pragma unroll
    for (int i = 0; i < 4; i++) {
        int mlo = wm + i * 16 + (lane >> 2);
        int mhi = mlo + 8;
        float a0 = g_bn_a[mlo], c0 = g_bn_b[mlo];
        float a1 = g_bn_a[mhi], c1 = g_bn_b[mhi];
        float rs0 = 0.f, rs1 = 0.f;
        size_t rowlo = ((size_t)b * CC + mlo) * HW;
        size_t rowhi = ((size_t)b * CC + mhi) * HW;
        #pragma unroll
        for (int j = 0; j < 4; j++) {
            int n = n0 + wn + j * 8 + (lane & 3) * 2;
            float y00 = fmaxf(fmaf(acc[i][j][0], a0, c0), 0.f);
            float y01 = fmaxf(fmaf(acc[i][j][1], a0, c0), 0.f);
            float y10 = fmaxf(fmaf(acc[i][j][2], a1, c1), 0.f);
            float y11 = fmaxf(fmaf(acc[i][j][3], a1, c1), 0.f);
            __half2 h0, h1, l0v, l1v;
            h0.x = __float2half(y00); h0.y = __float2half(y01);
            h1.x = __float2half(y10); h1.y = __float2half(y11);
            l0v.x = __float2half(y00 - __half2float(h0.x));
            l0v.y = __float2half(y01 - __half2float(h0.y));
            l1v.x = __float2half(y10 - __half2float(h1.x));
            l1v.y = __float2half(y11 - __half2float(h1.y));
            *(__half2*)&g_fhi[rowlo + n] = h0;
            *(__half2*)&g_fhi[rowhi + n] = h1;
            *(__half2*)&g_flo[rowlo + n] = l0v;
            *(__half2*)&g_flo[rowhi + n] = l1v;
            rs0 += y00 + y01; rs1 += y10 + y11;
        }
        rs0 += __shfl_xor_sync(0xFFFFFFFF, rs0, 1);
        rs0 += __shfl_xor_sync(0xFFFFFFFF, rs0, 2);
        rs1 += __shfl_xor_sync(0xFFFFFFFF, rs1, 1);
        rs1 += __shfl_xor_sync(0xFFFFFFFF, rs1, 2);
        if ((lane & 3) == 0) {
            atomicAdd(&g_fsum[b * CC + mlo], rs0);
            atomicAdd(&g_fsum[b * CC + mhi], rs1);
        }
    }
}

// ---------------------------------------------------------------
// K2: QK = Wqk @ feat via HMMA; 2-term split on Wqk, feat hi only.
// ---------------------------------------------------------------
#define QK_SMEM 66816
__global__ __launch_bounds__(256, 1) void k_qk_mma(const float* __restrict__ qb,
                                                   const float* __restrict__ kb) {
    extern __shared__ __align__(128) char smem[];
    const uint32_t smemb = smem_u32(smem);
    const int t    = threadIdx.x;
    const int lane = t & 31;
    const int wid  = t >> 5;
    const int n0   = blockIdx.x * 128;
    const int b    = blockIdx.y;
    const int wm   = (wid >> 2) * 32;
    const int wn   = (wid & 3) * 32;

    float acc[2][4][4];
    #pragma unroll
    for (int i = 0; i < 2; i++)
        #pragma unroll
        for (int j = 0; j < 4; j++)
            #pragma unroll
            for (int q = 0; q < 4; q++) acc[i][j][q] = 0.f;

    auto loadAB = [&](int kc, int s) {
        #pragma unroll
        for (int p = 0; p < 2; p++) {
            int idx = t + p * 256;
            int h = idx >> 8, rem = idx & 255;
            int r = rem >> 3, c = rem & 7;
            const __half* src = (h ? g_qkwlo : g_qkwhi) + (kc * 32 + r) * 64 + c * 8;
            CP_ASYNC16(smemb + s * 8192 + h * 4096 + r * 128 + ((c ^ (r & 7)) << 4), src);
        }
        #pragma unroll
        for (int p = 0; p < 2; p++) {
            int idx = t + p * 256;
            int r = idx >> 4, c = idx & 15;
            const __half* src = g_fhi + ((size_t)b * CC + kc * 32 + r) * HW + n0 + c * 8;
            CP_ASYNC16(smemb + 16384 + s * 8192 + r * 256 + ((c ^ (r & 7)) << 4), src);
        }
        CP_COMMIT();
    };

    loadAB(0, 0);

    for (int kc = 0; kc < 8; kc++) {
        const int s = kc & 1;
        if (kc < 7) { loadAB(kc + 1, s ^ 1); CP_WAIT(1); }
        else        { CP_WAIT(0); }
        __syncthreads();

        const int l = lane & 7, g = lane >> 3;
        #pragma unroll
        for (int ks8 = 0; ks8 < 2; ks8++) {
            const int ks = ks8 * 16;
            uint32_t Bf[4][2];
            #pragma unroll
            for (int jp = 0; jp < 2; jp++) {
                int r = ks + ((g & 1) << 3) + l;
                int c = (wn >> 3) + jp * 2 + (g >> 1);
                uint32_t ad = smemb + 16384 + s * 8192 + r * 256 + ((c ^ (r & 7)) << 4);
                uint32_t q0, q1, q2, q3;
                LDSM_X4_T(q0, q1, q2, q3, ad);
                Bf[jp*2][0]=q0; Bf[jp*2][1]=q1; Bf[jp*2+1][0]=q2; Bf[jp*2+1][1]=q3;
            }
            #pragma unroll
            for (int i = 0; i < 2; i++) {
                uint32_t Ah[4], Al[4];
                {
                    int r = ks + ((g >> 1) << 3) + l;
                    int c = ((wm + i * 16) >> 3) + (g & 1);
                    uint32_t boff = r * 128 + ((c ^ (r & 7)) << 4);
                    LDSM_X4_T(Ah[0], Ah[1], Ah[2], Ah[3], smemb + s * 8192 + boff);
                    LDSM_X4_T(Al[0], Al[1], Al[2], Al[3], smemb + s * 8192 + 4096 + boff);
                }
                #pragma unroll
                for (int j = 0; j < 4; j++) {
                    MMA16816(acc[i][j], Ah, Bf[j]);
                    MMA16816(acc[i][j], Al, Bf[j]);
                }
            }
        }
        __syncthreads();
    }

    float* qk = (float*)(smem + 32768);   // [64][129]
    #pragma unroll
    for (int i = 0; i < 2; i++) {
        int mlo = wm + i * 16 + (lane >> 2);
        int mhi = mlo + 8;
        float blo = (mlo < 32) ? qb[mlo] : kb[mlo - 32];
        float bhi = (mhi < 32) ? qb[mhi] : kb[mhi - 32];
        #pragma unroll
        for (int j = 0; j < 4; j++) {
            int col = wn + j * 8 + (lane & 3) * 2;
            qk[mlo * 129 + col]     = acc[i][j][0] + blo;
            qk[mlo * 129 + col + 1] = acc[i][j][1] + blo;
            qk[mhi * 129 + col]     = acc[i][j][2] + bhi;
            qk[mhi * 129 + col + 1] = acc[i][j][3] + bhi;
        }
    }
    __syncthreads();

    {
        int n = t & 127, h = t >> 7;
        float ss = 0.f;
        #pragma unroll
        for (int m = 0; m < 32; m++) { float v = qk[(h * 32 + m) * 129 + n]; ss = fmaf(v, v, ss); }
        float inv = rsqrtf(ss);
        size_t base = (size_t)b * CQ * HW + n0 + n;
        if (h == 0) {
            #pragma unroll
            for (int m = 0; m < 32; m++) {
                float v = qk[m * 129 + n] * inv;
                g_qnhi[base + (size_t)m * HW] = __float2half(v);
            }
        } else {
            #pragma unroll
            for (int m = 0; m < 32; m++) {
                float v = qk[(32 + m) * 129 + n] * inv;
                qk[(32 + m) * 129 + n] = v;
                __half vh = __float2half(v);
                g_knhi[base + (size_t)m * HW] = vh;
                g_knlo[base + (size_t)m * HW] = __float2half(v - __half2float(vh));
            }
        }
    }
    __syncthreads();
    float* part = (float*)(smem + 65792);  // [32][8]
    {
        int m = t >> 3, seg = t & 7;
        float s = 0.f;
        #pragma unroll
        for (int j = 0; j < 16; j++) s += qk[(32 + m) * 129 + seg * 16 + j];
        part[m * 8 + seg] = s;
    }
    __syncthreads();
    if (t < 32) {
        float s = 0.f;
        #pragma unroll
        for (int j = 0; j < 8; j++) s += part[t * 8 + j];
        atomicAdd(&g_knsum[b * CQ + t], s);
    }
}

// ---------------------------------------------------------------
// K3: G^T[c][m] = sum_n feat[c][n]*Kn[m][n]; 2-term split on Kn, feat hi.
// ---------------------------------------------------------------
#define G_SMEM 81920
__global__ __launch_bounds__(256, 1) void k_G_mma() {
    extern __shared__ __align__(128) char smem[];
    const uint32_t smemb = smem_u32(smem);
    const int t    = threadIdx.x;
    const int lane = t & 31;
    const int wid  = t >> 5;
    const int b    = blockIdx.y;
    const int n0   = blockIdx.x * 512;
    const int wc   = wid * 32;

    float acc[2][4][4];
    #pragma unroll
    for (int i = 0; i < 2; i++)
        #pragma unroll
        for (int j = 0; j < 4; j++)
            #pragma unroll
            for (int q = 0; q < 4; q++) acc[i][j][q] = 0.f;

    auto loadAB = [&](int kc, int s) {
        int nb = n0 + kc * 64;
        #pragma unroll
        for (int p = 0; p < 8; p++) {
            int idx = t + p * 256;
            int r = idx >> 3, c = idx & 7;
            const __half* src = g_fhi + ((size_t)b * CC + r) * HW + nb + c * 8;
            CP_ASYNC16(smemb + s * 32768 + r * 128 + ((c ^ (r & 7)) << 4), src);
        }
        #pragma unroll
        for (int p = 0; p < 2; p++) {
            int idx = t + p * 256;
            int h = idx >> 8, rem = idx & 255;
            int r = rem >> 3, c = rem & 7;
            const __half* src = (h ? g_knlo : g_knhi)
                + ((size_t)b * CQ + r) * HW + nb + c * 8;
            CP_ASYNC16(smemb + 65536 + s * 8192 + h * 4096 + r * 128 + ((c ^ (r & 7)) << 4), src);
        }
        CP_COMMIT();
    };

    loadAB(0, 0);

    for (int kc = 0; kc < 8; kc++) {
        const int s = kc & 1;
        if (kc < 7) { loadAB(kc + 1, s ^ 1); CP_WAIT(1); }
        else        { CP_WAIT(0); }
        __syncthreads();

        #pragma unroll
        for (int ks8 = 0; ks8 < 4; ks8++) {
            const int kcol0 = ks8 * 2;
            uint32_t Bh[4][2], Bl[4][2];
            #pragma unroll
            for (int h = 0; h < 2; h++)
                #pragma unroll
                for (int jp = 0; jp < 2; jp++) {
                    int r = jp * 16 + ((lane & 16) >> 1) + (lane & 7);
                    int c = kcol0 + ((lane & 8) >> 3);
                    uint32_t ad = smemb + 65536 + s * 8192 + h * 4096
                                + r * 128 + ((c ^ (r & 7)) << 4);
                    uint32_t q0, q1, q2, q3;
                    LDSM_X4(q0, q1, q2, q3, ad);
                    if (h == 0) { Bh[jp*2][0]=q0; Bh[jp*2][1]=q1; Bh[jp*2+1][0]=q2; Bh[jp*2+1][1]=q3; }
                    else        { Bl[jp*2][0]=q0; Bl[jp*2][1]=q1; Bl[jp*2+1][0]=q2; Bl[jp*2+1][1]=q3; }
                }
            #pragma unroll
            for (int i = 0; i < 2; i++) {
                uint32_t Ah[4];
                {
                    int r = wc + i * 16 + (lane & 15);
                    int c = kcol0 + ((lane & 16) >> 4);
                    uint32_t boff = r * 128 + ((c ^ (r & 7)) << 4);
                    LDSM_X4(Ah[0], Ah[1], Ah[2], Ah[3], smemb + s * 32768 + boff);
                }
                #pragma unroll
                for (int j = 0; j < 4; j++) {
                    MMA16816(acc[i][j], Ah, Bh[j]);
                    MMA16816(acc[i][j], Ah, Bl[j]);
                }
            }
        }
        __syncthreads();
    }

    #pragma unroll
    for (int i = 0; i < 2; i++) {
        int clo = wc + i * 16 + (lane >> 2);
        int chi = clo + 8;
        #pragma unroll
        for (int j = 0; j < 4; j++) {
            int m = j * 8 + (lane & 3) * 2;
            atomicAdd(&g_G[((size_t)b * CQ + m)     * CC + clo], acc[i][j][0]);
            atomicAdd(&g_G[((size_t)b * CQ + m + 1) * CC + clo], acc[i][j][1]);
            atomicAdd(&g_G[((size_t)b * CQ + m)     * CC + chi], acc[i][j][2]);
            atomicAdd(&g_G[((size_t)b * CQ + m + 1) * CC + chi], acc[i][j][3]);
        }
    }
}

// ---------------------------------------------------------------
// K4: matrix = G @ v_w^T + v_b x knsum -> fp16 hi/lo [c][m];
//     vsum = v_w @ fsum + N*v_b.  grid (8 c-tiles, 16 b).
// ---------------------------------------------------------------
#define MAT_SMEM 68096
__global__ __launch_bounds__(256, 1) void k_matrix(const float* __restrict__ vw,
                                                   const float* __restrict__ vb) {
    extern __shared__ __align__(16) float sm[];
    float* GsT   = sm;                        // [256][33]
    float* vws   = sm + 256 * 33;             // [32][260]
    float* fsums = sm + 256 * 33 + 32 * 260;  // [256]
    const int t  = threadIdx.x;
    const int b  = blockIdx.y;
    const int c0 = blockIdx.x * 32;

    {
        int rr = t >> 3, kseg = (t & 7) * 32;
        const float* gp = g_G + ((size_t)b * CQ + rr) * CC + kseg;
        #pragma unroll
        for (int j = 0; j < 8; j++) {
            float4 v = *(const float4*)&gp[j * 4];
            GsT[(kseg + j*4 + 0) * 33 + rr] = v.x;
            GsT[(kseg + j*4 + 1) * 33 + rr] = v.y;
            GsT[(kseg + j*4 + 2) * 33 + rr] = v.z;
            GsT[(kseg + j*4 + 3) * 33 + rr] = v.w;
        }
        const float* vp = vw + (size_t)(c0 + rr) * CC + kseg;
        #pragma unroll
        for (int j = 0; j < 8; j++)
            *(float4*)&vws[rr * 260 + kseg + j * 4] = *(const float4*)&vp[j * 4];
    }
    fsums[t] = g_fsum[b * CC + t];
    __syncthreads();

    const int m = t & 31;
    const int w = t >> 5;
    float acc[4] = {0.f, 0.f, 0.f, 0.f};
    #pragma unroll 4
    for (int k = 0; k < CC; k++) {
        float gv = GsT[k * 33 + m];
        #pragma unroll
        for (int j = 0; j < 4; j++)
            acc[j] = fmaf(gv, vws[(w * 4 + j) * 260 + k], acc[j]);
    }
    float vs[4] = {0.f, 0.f, 0.f, 0.f};
    for (int k = m; k < CC; k += 32) {
        float fv = fsums[k];
        #pragma unroll
        for (int j = 0; j < 4; j++)
            vs[j] = fmaf(vws[(w * 4 + j) * 260 + k], fv, vs[j]);
    }
    #pragma unroll
    for (int j = 0; j < 4; j++)
        #pragma unroll
        for (int o = 16; o; o >>= 1)
            vs[j] += __shfl_xor_sync(0xFFFFFFFF, vs[j], o);

    float kn = g_knsum[b * CQ + m];
    #pragma unroll
    for (int j = 0; j < 4; j++) {
        int c = c0 + w * 4 + j;
        float val = acc[j] + vb[c] * kn;
        __half hi = __float2half(val);
        size_t idx = ((size_t)b * CC + c) * CQ + m;
        g_mthi[idx] = hi;
        g_mtlo[idx] = __float2half(val - __half2float(hi));
        if (m == 0) g_vsum[b * CC + c] = vs[j] + NPIXF * vb[c];
    }
}

// ---------------------------------------------------------------
// K5: ms = matrix^T @ Qn + vsum; 2-term split on mt, Qn hi only. (R14 version)
// ---------------------------------------------------------------
#define FIN_SMEM 75264
__global__ __launch_bounds__(512, 1) void k_final_mma(const float* __restrict__ gamma,
                                                      float* __restrict__ out) {
    extern __shared__ __align__(128) char smem[];
    const uint32_t smemb = smem_u32(smem);
    const int t    = threadIdx.x;
    const int lane = t & 31;
    const int wid  = t >> 5;
    const int n0   = blockIdx.x * 128;
    const int b    = blockIdx.y;
    const int wm   = (wid >> 2) * 64;
    const int wn   = (wid & 3) * 32;

    float* tails = (float*)(smem + 73728);
    float* vsums = (float*)(smem + 74240);

    #pragma unroll
    for (int p = 0; p < 4; p++) {        // A: mt 2048 ops
        int idx = t + p * 512;
        int h = idx >> 10, rem = idx & 1023;
        int r = rem >> 2, c = rem & 3;
        const __half* src = (h ? g_mtlo : g_mthi) + ((size_t)b * CC + r) * CQ + c * 8;
        CP_ASYNC16(smemb + h * 32768 + r * 128 + ((c ^ (r & 7)) << 4), src);
    }
    {                                    // B: qnhi 512 ops
        int r = t >> 4, c = t & 15;
        const __half* src = g_qnhi + ((size_t)b * CQ + r) * HW + n0 + c * 8;
        CP_ASYNC16(smemb + 65536 + r * 256 + ((c ^ (r & 7)) << 4), src);
    }
    CP_COMMIT();
    if (t < 256) vsums[t] = g_vsum[b * CC + t];
    CP_WAIT(0);
    __syncthreads();

    if (t < 128) {
        int n = t;
        int cseg = n >> 3, off = (n & 7) * 2;
        float s = 0.f;
        #pragma unroll
        for (int m = 0; m < 32; m++) {
            uint32_t ad = 65536 + m * 256 + ((cseg ^ (m & 7)) << 4) + off;
            float qh = __half2float(*(__half*)(smem + ad));
            s = fmaf(qh, g_knsum[b * CQ + m] + 1e-6f, s);
        }
        tails[n] = 1.0f / (NPIXF + s);
    }
    __syncthreads();

    float acc[4][4][4];
    #pragma unroll
    for (int i = 0; i < 4; i++)
        #pragma unroll
        for (int j = 0; j < 4; j++)
            #pragma unroll
            for (int q = 0; q < 4; q++) acc[i][j][q] = 0.f;

    const int l = lane & 7, g = lane >> 3;
    #pragma unroll
    for (int ks8 = 0; ks8 < 2; ks8++) {
        const int ks = ks8 * 16;
        uint32_t Bf[4][2];
        #pragma unroll
        for (int jp = 0; jp < 2; jp++) {
            int r = ks + ((g & 1) << 3) + l;
            int c = (wn >> 3) + jp * 2 + (g >> 1);
            uint32_t ad = smemb + 65536 + r * 256 + ((c ^ (r & 7)) << 4);
            uint32_t q0, q1, q2, q3;
            LDSM_X4_T(q0, q1, q2, q3, ad);
            Bf[jp*2][0]=q0; Bf[jp*2][1]=q1; Bf[jp*2+1][0]=q2; Bf[jp*2+1][1]=q3;
        }
        #pragma unroll
        for (int i = 0; i < 4; i++) {
            uint32_t Ah[4], Al[4];
            {
                int r = wm + i * 16 + (lane & 15);
                int c = ks8 * 2 + ((lane & 16) >> 4);
                uint32_t boff = r * 128 + ((c ^ (r & 7)) << 4);
                LDSM_X4(Ah[0], Ah[1], Ah[2], Ah[3], smemb + boff);
                LDSM_X4(Al[0], Al[1], Al[2], Al[3], smemb + 32768 + boff);
            }
            #pragma unroll
            for (int j = 0; j < 4; j++) {
                MMA16816(acc[i][j], Ah, Bf[j]);
                MMA16816(acc[i][j], Al, Bf[j]);
            }
        }
    }

    const float gw = gamma[0];
    #pragma unroll
    for (int i = 0; i < 4; i++) {
        int clo = wm + i * 16 + (lane >> 2);
        int chi = clo + 8;
        float vs0 = vsums[clo], vs1 = vsums[chi];
        size_t rowlo = ((size_t)b * CC + clo) * HW;
        size_t rowhi = ((size_t)b * CC + chi) * HW;
        #pragma unroll
        for (int j = 0; j < 4; j++) {
            int nl = wn + j * 8 + (lane & 3) * 2;
            int n  = n0 + nl;
            float t0 = tails[nl], t1 = tails[nl + 1];
            __half2 fh0 = *(__half2*)&g_fhi[rowlo + n];
            __half2 fl0 = *(__half2*)&g_flo[rowlo + n];
            __half2 fh1 = *(__half2*)&g_fhi[rowhi + n];
            __half2 fl1 = *(__half2*)&g_flo[rowhi + n];
            float f00 = __half2float(fh0.x) + __half2float(fl0.x);
            float f01 = __half2float(fh0.y) + __half2float(fl0.y);
            float f10 = __half2float(fh1.x) + __half2float(fl1.x);
            float f11 = __half2float(fh1.y) + __half2float(fl1.y);
            float w00 = (acc[i][j][0] + vs0) * t0;
            float w01 = (acc[i][j][1] + vs0) * t1;
            float w10 = (acc[i][j][2] + vs1) * t0;
            float w11 = (acc[i][j][3] + vs1) * t1;
            float2 o0, o1;
            o0.x = fmaf(f00, fmaf(gw, w00, f00), f00);
            o0.y = fmaf(f01, fmaf(gw, w01, f01), f01);
            o1.x = fmaf(f10, fmaf(gw, w10, f10), f10);
            o1.y = fmaf(f11, fmaf(gw, w11, f11), f11);
            *(float2*)&out[rowlo + n] = o0;
            *(float2*)&out[rowhi + n] = o1;
        }
    }
}

// ---------------------------------------------------------------
extern "C" void kernel_launch(void* const* d_in, const int* in_sizes, int n_in,
                              void* d_out, int out_size) {
    const float* fsp      = (const float*)d_in[0];
    const float* fcp      = (const float*)d_in[1];
    const float* conv_w   = (const float*)d_in[2];
    const float* bn_scale = (const float*)d_in[3];
    const float* bn_bias  = (const float*)d_in[4];
    const float* bn_mean  = (const float*)d_in[5];
    const float* bn_var   = (const float*)d_in[6];
    const float* gamma    = (const float*)d_in[7];
    const float* q_w      = (const float*)d_in[8];
    const float* q_b      = (const float*)d_in[9];
    const float* k_w      = (const float*)d_in[10];
    const float* k_b      = (const float*)d_in[11];
    const float* v_w      = (const float*)d_in[12];
    const float* v_b      = (const float*)d_in[13];
    float* out = (float*)d_out;

    cudaFuncSetAttribute(k_conv_mma,  cudaFuncAttributeMaxDynamicSharedMemorySize, CONV_SMEM);
    cudaFuncSetAttribute(k_qk_mma,    cudaFuncAttributeMaxDynamicSharedMemorySize, QK_SMEM);
    cudaFuncSetAttribute(k_G_mma,     cudaFuncAttributeMaxDynamicSharedMemorySize, G_SMEM);
    cudaFuncSetAttribute(k_matrix,    cudaFuncAttributeMaxDynamicSharedMemorySize, MAT_SMEM);
    cudaFuncSetAttribute(k_final_mma, cudaFuncAttributeMaxDynamicSharedMemorySize, FIN_SMEM);

    k_setup<<<128, 256>>>(bn_scale, bn_bias, bn_mean, bn_var, conv_w, q_w, k_w);
    k_conv_mma <<<dim3(72, 16), 512, CONV_SMEM>>>(fsp, fcp);
    k_qk_mma   <<<dim3(72, 16), 256, QK_SMEM>>>(q_b, k_b);
    k_G_mma    <<<dim3(18, 16), 256, G_SMEM>>>();
    k_matrix   <<<dim3(8, 16),  256, MAT_SMEM>>>(v_w, v_b);
    k_final_mma<<<dim3(72, 16), 512, FIN_SMEM>>>(gamma, out);
}